// round 13
// baseline (speedup 1.0000x reference)
#include <cuda_runtime.h>
#include <math.h>

#define NBINS 1001
#define KQ 127
#define HALFB 500
#define EPS_S 1e-4
#define IMIN 63
#define NCAND 438
#define HIST_SUB 4
#define EXP_CUT -700.0
#define BAND 2e-3f
#define MAIN_GRID 592   // 4 blocks/SM x 148 SMs; __launch_bounds__(256,4) guarantees residency

__device__ unsigned int g_absmax_bits;   // zero at load; final kl block re-zeroes
__device__ unsigned int g_hist[NBINS];   // zero at load; final kl block re-zeroes
__device__ unsigned int g_csum[NBINS + 1];
__device__ unsigned int g_total;
__device__ unsigned int g_bar;           // grid barrier counter (reset by kl final block)
__device__ unsigned int g_done;          // hist scan ticket (reset by kl final block)
__device__ unsigned int g_done2;         // kl argmin ticket (reset by kl final block)
__device__ double g_kl[NCAND];

// ---------------- binning ----------------
// Fast path: fp32 estimate floor((c+a)*inv); provably correct unless the
// fractional part is within BAND of a boundary (estimate+edge error < 3.5e-4
// bins), in which case verify against exact fp32 linspace edges.
__device__ __forceinline__ int bin_of(float c, float a, float inv, float step) {
    float y = __fmul_rn(__fadd_rn(c, a), inv);
    int b = (int)y;
    float fr = y - (float)b;
    if (fr < BAND || fr > 1.0f - BAND) {
        float e0 = __fadd_rn(__fmul_rn((float)b, step), -a);
        float e1 = __fadd_rn(__fmul_rn((float)(b + 1), step), -a);
        b += (c >= e1) ? 1 : 0;
        b -= (c < e0) ? 1 : 0;
    }
    return max(0, min(NBINS - 1, b));
}

// ---------------- fused absmax + grid barrier + histogram + scan ----------------
__global__ void __launch_bounds__(256, 4) main_kernel(const float* __restrict__ x, int n) {
    __shared__ unsigned int sh[HIST_SUB][NBINS];
    unsigned int* shf = &sh[0][0];
    for (int k = threadIdx.x; k < HIST_SUB * NBINS; k += 256) shf[k] = 0u;

    const int n4 = n >> 2;
    const float4* x4 = (const float4*)x;
    const int G = gridDim.x;
    const int b = blockIdx.x;
    const int lo = (int)((long long)b * n4 / G);
    const int hi = (int)((long long)(b + 1) * n4 / G);
    int lane = threadIdx.x & 31, w = threadIdx.x >> 5;

    // ---- phase 1: absmax over own chunk (forward sweep) ----
    float m = 0.f;
    for (int idx = lo + threadIdx.x; idx < hi; idx += 256) {
        float4 v = x4[idx];
        m = fmaxf(m, fmaxf(fmaxf(fabsf(v.x), fabsf(v.y)), fmaxf(fabsf(v.z), fabsf(v.w))));
    }
    if (b == 0 && threadIdx.x < (n & 3))
        m = fmaxf(m, fabsf(x[n4 * 4 + threadIdx.x]));
    #pragma unroll
    for (int o = 16; o; o >>= 1) m = fmaxf(m, __shfl_xor_sync(0xffffffffu, m, o));
    __shared__ float sm[8];
    if (lane == 0) sm[w] = m;
    __syncthreads();
    if (w == 0) {
        m = (lane < 8) ? sm[lane] : 0.f;
        #pragma unroll
        for (int o = 4; o; o >>= 1) m = fmaxf(m, __shfl_xor_sync(0xffffffffu, m, o));
        if (lane == 0) atomicMax(&g_absmax_bits, __float_as_uint(m));
    }

    // ---- grid barrier (all blocks resident by __launch_bounds__(256,4)) ----
    __threadfence();
    __syncthreads();
    if (threadIdx.x == 0) {
        atomicAdd(&g_bar, 1u);
        while (*(volatile unsigned int*)&g_bar < (unsigned int)G) { }
    }
    __syncthreads();

    const float a = __uint_as_float(*(volatile unsigned int*)&g_absmax_bits);
    const float step = __fdiv_rn(__fmul_rn(2.0f, a), (float)NBINS);
    const float inv = __fdiv_rn((float)NBINS, __fmul_rn(2.0f, a));
    // lane-indexed sub-histogram: conflicting lanes spread over 4 copies
    unsigned int* hsub = sh[threadIdx.x & (HIST_SUB - 1)];

    // ---- phase 2: histogram over own chunk, REVERSE sweep (LIFO L2 reuse) ----
    for (int idx = hi - 1 - threadIdx.x; idx >= lo; idx -= 256) {
        float4 v = x4[idx];
        atomicAdd(&hsub[bin_of(v.x, a, inv, step)], 1u);
        atomicAdd(&hsub[bin_of(v.y, a, inv, step)], 1u);
        atomicAdd(&hsub[bin_of(v.z, a, inv, step)], 1u);
        atomicAdd(&hsub[bin_of(v.w, a, inv, step)], 1u);
    }
    if (b == 0 && threadIdx.x < (n & 3)) {
        float c = x[n4 * 4 + threadIdx.x];
        atomicAdd(&hsub[bin_of(c, a, inv, step)], 1u);
    }
    __syncthreads();
    for (int k = threadIdx.x; k < NBINS; k += 256) {
        unsigned int s = 0;
        #pragma unroll
        for (int j = 0; j < HIST_SUB; j++) s += sh[j][k];
        if (s) atomicAdd(&g_hist[k], s);
    }

    // ---- fused scan: last block to finish builds the exclusive prefix ----
    __shared__ unsigned int s_last;
    __threadfence();
    if (threadIdx.x == 0)
        s_last = (atomicAdd(&g_done, 1u) == (unsigned int)(G - 1)) ? 1u : 0u;
    __syncthreads();
    if (s_last) {
        __threadfence();
        __shared__ unsigned int tsum[256];
        __shared__ unsigned int wex[9];
        int t = threadIdx.x;
        unsigned int hv[4], loc[4];
        unsigned int s = 0;
        #pragma unroll
        for (int j = 0; j < 4; j++) {
            int k = 4 * t + j;
            hv[j] = (k < NBINS) ? *(volatile unsigned int*)&g_hist[k] : 0u;
            loc[j] = s;
            s += hv[j];
        }
        tsum[t] = s;
        __syncthreads();
        unsigned int v = tsum[t];
        unsigned int inc = v;
        #pragma unroll
        for (int o = 1; o < 32; o <<= 1) {
            unsigned int q = __shfl_up_sync(0xffffffffu, inc, o);
            if (lane >= o) inc += q;
        }
        if (lane == 31) wex[w + 1] = inc;
        __syncthreads();
        if (t == 0) {
            wex[0] = 0u;
            for (int j = 1; j < 8; j++) wex[j + 1] += wex[j];
        }
        __syncthreads();
        unsigned int base = wex[w] + inc - v;
        #pragma unroll
        for (int j = 0; j < 4; j++) {
            int k = 4 * t + j;
            if (k < NBINS) g_csum[k] = base + loc[j];
        }
        if (t == 255) {
            unsigned int tot = base + loc[3] + hv[3];
            g_csum[NBINS] = tot;
            g_total = tot;
        }
    }
}

// ---------------- reductions ----------------
template <typename T>
__device__ __forceinline__ T warpSumT(T v) {
    #pragma unroll
    for (int o = 16; o; o >>= 1) v += __shfl_xor_sync(0xffffffffu, v, o);
    return v;
}
__device__ __forceinline__ unsigned int warpMaxU(unsigned int v) {
    #pragma unroll
    for (int o = 16; o; o >>= 1) v = max(v, __shfl_xor_sync(0xffffffffu, v, o));
    return v;
}
__device__ __forceinline__ double warpMaxD(double v) {
    #pragma unroll
    for (int o = 16; o; o >>= 1) v = fmax(v, __shfl_xor_sync(0xffffffffu, v, o));
    return v;
}

struct RedShared {
    double d[16];
    unsigned long long u[8];
};

__device__ __forceinline__ double blockSumD(double v, RedShared* sh) {
    int lane = threadIdx.x & 31, w = threadIdx.x >> 5;
    v = warpSumT(v);
    if (lane == 0) sh->d[w] = v;
    __syncthreads();
    if (w == 0) {
        double t = (lane < 8) ? sh->d[lane] : 0.0;
        t = warpSumT(t);
        if (lane == 0) sh->d[0] = t;
    }
    __syncthreads();
    double r = sh->d[0];
    __syncthreads();
    return r;
}
__device__ __forceinline__ void blockSum2(double& a, double& b, RedShared* sh) {
    int lane = threadIdx.x & 31, w = threadIdx.x >> 5;
    a = warpSumT(a); b = warpSumT(b);
    if (lane == 0) { sh->d[w] = a; sh->d[8 + w] = b; }
    __syncthreads();
    if (w == 0) {
        double ta = (lane < 8) ? sh->d[lane] : 0.0;
        double tb = (lane < 8) ? sh->d[8 + lane] : 0.0;
        ta = warpSumT(ta); tb = warpSumT(tb);
        if (lane == 0) { sh->d[0] = ta; sh->d[8] = tb; }
    }
    __syncthreads();
    a = sh->d[0]; b = sh->d[8];
    __syncthreads();
}
__device__ __forceinline__ void blockSumU_MaxD(unsigned int& s, double& mx, RedShared* sh) {
    int lane = threadIdx.x & 31, w = threadIdx.x >> 5;
    s = warpSumT(s); mx = warpMaxD(mx);
    if (lane == 0) { sh->u[w] = s; sh->d[w] = mx; }
    __syncthreads();
    if (w == 0) {
        unsigned int ts = (lane < 8) ? (unsigned int)sh->u[lane] : 0u;
        double tm = (lane < 8) ? sh->d[lane] : -1e300;
        ts = warpSumT(ts); tm = warpMaxD(tm);
        if (lane == 0) { sh->u[0] = ts; sh->d[0] = tm; }
    }
    __syncthreads();
    s = (unsigned int)sh->u[0]; mx = sh->d[0];
    __syncthreads();
}
__device__ __forceinline__ unsigned int blockMaxU(unsigned int v, RedShared* sh) {
    int lane = threadIdx.x & 31, w = threadIdx.x >> 5;
    v = warpMaxU(v);
    if (lane == 0) sh->u[w] = v;
    __syncthreads();
    if (w == 0) {
        unsigned int t = (lane < 8) ? (unsigned int)sh->u[lane] : 0u;
        t = warpMaxU(t);
        if (lane == 0) sh->u[0] = t;
    }
    __syncthreads();
    unsigned int r = (unsigned int)sh->u[0];
    __syncthreads();
    return r;
}

// ---------------- per-candidate KL + fused argmin/reset ----------------
__global__ void kl_kernel(float* __restrict__ out) {
    const int i = IMIN + (int)blockIdx.x;
    const int L = 2 * i + 1;
    const int start = HALFB - i;
    const int stop = HALFB + i + 1;
    const int m = L / KQ;

    __shared__ unsigned int s_h[NBINS];
    __shared__ double s_q[KQ];
    __shared__ unsigned int s_nm[KQ];
    __shared__ RedShared s_red;

    for (int k = threadIdx.x; k < NBINS; k += 256) s_h[k] = g_hist[k];
    __syncthreads();

    const unsigned int left = g_csum[start];
    const unsigned int right = g_total - g_csum[stop];

    unsigned int pv[4], vv[4];
    unsigned int mpi = 0u;
    #pragma unroll
    for (int t = 0; t < 4; t++) {
        int k = threadIdx.x + t * 256;
        pv[t] = 0u; vv[t] = 0u;
        if (k < L) {
            unsigned int v = s_h[start + k];
            vv[t] = v;
            unsigned int p = v;
            if (k == 0) p += left;
            if (k == L - 1) p += right;
            pv[t] = p;
            mpi = max(mpi, p);
        }
    }
    mpi = blockMaxU(mpi, &s_red);
    const double mp = mpi ? (double)mpi : EPS_S;

    double qseg = 0.0;
    unsigned int nmj = 0u;
    if (threadIdx.x < KQ) {
        int j = threadIdx.x;
        int k0 = j * m;
        int k1 = (j == KQ - 1) ? L : (k0 + m);
        unsigned int sum = 0u, cnt = 0u;
        for (int k = k0; k < k1; k++) {
            unsigned int v = s_h[start + k];
            sum += v;
            cnt += (v != 0u && k != L - 1) ? 1u : 0u;
        }
        nmj = cnt;
        if (cnt > 0u) qseg = (double)sum / (double)cnt;
        s_q[j] = qseg;
        s_nm[j] = cnt;
    }
    unsigned int nnzq = nmj;
    double mq = (threadIdx.x < KQ && nmj > 0u) ? qseg : -1e300;
    blockSumU_MaxD(nnzq, mq, &s_red);
    mq = fmax(mq, EPS_S);

    double sq = 0.0;
    if (threadIdx.x < KQ && nmj > 0u) {
        double dq = qseg - mq;
        if (dq > EXP_CUT) sq = (double)nmj * exp(dq);
    }
    if (threadIdx.x == 0) {
        double dz = EPS_S - mq;
        if (dz > EXP_CUT) sq += (double)(L - (int)nnzq) * exp(dz);
    }
    // sp: integer gate (inclusion of borderline bins is harmless: terms < e^-700)
    double sp = 0.0;
    {
        unsigned int gate_u = (mpi > 700u) ? (mpi - 700u) : 0u;
        #pragma unroll
        for (int t = 0; t < 4; t++) {
            int k = threadIdx.x + t * 256;
            if (k < L && pv[t] >= gate_u) {
                double pl = pv[t] ? (double)pv[t] : EPS_S;
                sp += exp(pl - mp);
            }
        }
    }
    blockSum2(sp, sq, &s_red);
    const double lZp = mp + log(sp);
    const double lZq = mq + log(sq);

    double kl = 0.0;
    {
        double g2 = lZp + EXP_CUT;
        unsigned int gate2 = (g2 <= 0.0) ? 0u : (unsigned int)g2;  // floor; inclusive
        #pragma unroll
        for (int t = 0; t < 4; t++) {
            int k = threadIdx.x + t * 256;
            if (k < L && pv[t] >= gate2) {
                double pl = pv[t] ? (double)pv[t] : EPS_S;
                int seg = min(k / m, KQ - 1);
                bool assigned = (vv[t] != 0u) && (k != L - 1) && (s_nm[seg] > 0u);
                double ql = assigned ? s_q[seg] : EPS_S;
                double lp = pl - lZp;
                double lq = ql - lZq;
                kl += exp(lp) * (lp - lq);
            }
        }
    }
    kl = blockSumD(kl, &s_red);
    if (threadIdx.x == 0)
        g_kl[blockIdx.x] = (nnzq > 0u) ? kl : (double)INFINITY;

    // ---- fused argmin + output + global-state reset (last block) ----
    __shared__ unsigned int s_fin;
    __threadfence();
    if (threadIdx.x == 0)
        s_fin = (atomicAdd(&g_done2, 1u) == (unsigned int)(gridDim.x - 1)) ? 1u : 0u;
    __syncthreads();
    if (s_fin) {
        __threadfence();
        __shared__ double sv[256];
        __shared__ int si[256];
        double best = (double)INFINITY;
        int bi = 0x7fffffff;
        for (int k = threadIdx.x; k < NCAND; k += 256) {
            double v = *(volatile double*)&g_kl[k];
            if (v < best || (v == best && k < bi)) { best = v; bi = k; }
        }
        sv[threadIdx.x] = best; si[threadIdx.x] = bi;
        __syncthreads();
        for (int s = 128; s > 0; s >>= 1) {
            if (threadIdx.x < s) {
                double vo = sv[threadIdx.x + s];
                int io = si[threadIdx.x + s];
                if (vo < sv[threadIdx.x] || (vo == sv[threadIdx.x] && io < si[threadIdx.x])) {
                    sv[threadIdx.x] = vo; si[threadIdx.x] = io;
                }
            }
            __syncthreads();
        }
        if (threadIdx.x == 0) {
            int ib = IMIN + si[0];
            float a = __uint_as_float(g_absmax_bits);
            double thr = -(double)a + 2.0 * (double)a * (double)(ib + HALFB + 1) / (double)NBINS;
            out[0] = (float)thr;
            // reset all global state for the next call/replay
            g_absmax_bits = 0u;
            g_bar = 0u;
            g_done = 0u;
            g_done2 = 0u;
        }
        for (int k = threadIdx.x; k < NBINS; k += 256) g_hist[k] = 0u;
    }
}

extern "C" void kernel_launch(void* const* d_in, const int* in_sizes, int n_in,
                              void* d_out, int out_size) {
    const float* x = (const float*)d_in[0];
    int n = in_sizes[0];
    main_kernel<<<MAIN_GRID, 256>>>(x, n);
    kl_kernel<<<NCAND, 256>>>((float*)d_out);
}

// round 14
// speedup vs baseline: 1.1935x; 1.1935x over previous
#include <cuda_runtime.h>
#include <math.h>

#define NBINS 1001
#define KQ 127
#define HALFB 500
#define EPS_S 1e-4
#define IMIN 63
#define NCAND 438
#define HIST_SUB 4
#define EXP_CUT -700.0
#define BAND 2e-3f
#define MAIN_GRID 592   // 4 blocks/SM x 148 SMs; __launch_bounds__(256,4) guarantees residency
#define KLT 512         // kl block size (2 bins/thread); raises grid-limited occupancy 2x

__device__ unsigned int g_absmax_bits;   // zero at load; final kl block re-zeroes
__device__ unsigned int g_hist[NBINS];   // zero at load; final kl block re-zeroes
__device__ unsigned int g_csum[NBINS + 1];
__device__ unsigned int g_total;
__device__ unsigned int g_bar;           // grid barrier counter (reset by kl final block)
__device__ unsigned int g_done;          // hist scan ticket (reset by kl final block)
__device__ unsigned int g_done2;         // kl argmin ticket (reset by kl final block)
__device__ double g_kl[NCAND];

// ---------------- binning ----------------
__device__ __forceinline__ int bin_of(float c, float a, float inv, float step) {
    float y = __fmul_rn(__fadd_rn(c, a), inv);
    int b = (int)y;
    float fr = y - (float)b;
    if (fr < BAND || fr > 1.0f - BAND) {
        float e0 = __fadd_rn(__fmul_rn((float)b, step), -a);
        float e1 = __fadd_rn(__fmul_rn((float)(b + 1), step), -a);
        b += (c >= e1) ? 1 : 0;
        b -= (c < e0) ? 1 : 0;
    }
    return max(0, min(NBINS - 1, b));
}

// ---------------- fused absmax + grid barrier + histogram + scan (EXACT R10) ----------------
__global__ void __launch_bounds__(256, 4) main_kernel(const float* __restrict__ x, int n) {
    __shared__ unsigned int sh[HIST_SUB][NBINS];
    unsigned int* shf = &sh[0][0];
    for (int k = threadIdx.x; k < HIST_SUB * NBINS; k += 256) shf[k] = 0u;

    const int n4 = n >> 2;
    const float4* x4 = (const float4*)x;
    const int G = gridDim.x;
    const int b = blockIdx.x;
    const int lo = (int)((long long)b * n4 / G);
    const int hi = (int)((long long)(b + 1) * n4 / G);
    int lane = threadIdx.x & 31, w = threadIdx.x >> 5;

    // ---- phase 1: absmax over own chunk (forward sweep) ----
    float m = 0.f;
    for (int idx = lo + threadIdx.x; idx < hi; idx += 256) {
        float4 v = x4[idx];
        m = fmaxf(m, fmaxf(fmaxf(fabsf(v.x), fabsf(v.y)), fmaxf(fabsf(v.z), fabsf(v.w))));
    }
    if (b == 0 && threadIdx.x < (n & 3))
        m = fmaxf(m, fabsf(x[n4 * 4 + threadIdx.x]));
    #pragma unroll
    for (int o = 16; o; o >>= 1) m = fmaxf(m, __shfl_xor_sync(0xffffffffu, m, o));
    __shared__ float sm[8];
    if (lane == 0) sm[w] = m;
    __syncthreads();
    if (w == 0) {
        m = (lane < 8) ? sm[lane] : 0.f;
        #pragma unroll
        for (int o = 4; o; o >>= 1) m = fmaxf(m, __shfl_xor_sync(0xffffffffu, m, o));
        if (lane == 0) atomicMax(&g_absmax_bits, __float_as_uint(m));
    }

    // ---- grid barrier ----
    __threadfence();
    __syncthreads();
    if (threadIdx.x == 0) {
        atomicAdd(&g_bar, 1u);
        while (*(volatile unsigned int*)&g_bar < (unsigned int)G) { }
    }
    __syncthreads();

    const float a = __uint_as_float(*(volatile unsigned int*)&g_absmax_bits);
    const float step = __fdiv_rn(__fmul_rn(2.0f, a), (float)NBINS);
    const float inv = __fdiv_rn((float)NBINS, __fmul_rn(2.0f, a));
    unsigned int* hsub = sh[(threadIdx.x >> 5) & (HIST_SUB - 1)];

    // ---- phase 2: histogram over own chunk, REVERSE sweep (LIFO L2 reuse) ----
    for (int idx = hi - 1 - threadIdx.x; idx >= lo; idx -= 256) {
        float4 v = x4[idx];
        atomicAdd(&hsub[bin_of(v.x, a, inv, step)], 1u);
        atomicAdd(&hsub[bin_of(v.y, a, inv, step)], 1u);
        atomicAdd(&hsub[bin_of(v.z, a, inv, step)], 1u);
        atomicAdd(&hsub[bin_of(v.w, a, inv, step)], 1u);
    }
    if (b == 0 && threadIdx.x < (n & 3)) {
        float c = x[n4 * 4 + threadIdx.x];
        atomicAdd(&hsub[bin_of(c, a, inv, step)], 1u);
    }
    __syncthreads();
    for (int k = threadIdx.x; k < NBINS; k += 256) {
        unsigned int s = 0;
        #pragma unroll
        for (int j = 0; j < HIST_SUB; j++) s += sh[j][k];
        if (s) atomicAdd(&g_hist[k], s);
    }

    // ---- fused scan: last block builds exclusive prefix ----
    __shared__ unsigned int s_last;
    __threadfence();
    if (threadIdx.x == 0)
        s_last = (atomicAdd(&g_done, 1u) == (unsigned int)(G - 1)) ? 1u : 0u;
    __syncthreads();
    if (s_last) {
        __threadfence();
        __shared__ unsigned int tsum[256];
        __shared__ unsigned int wex[9];
        int t = threadIdx.x;
        unsigned int hv[4], loc[4];
        unsigned int s = 0;
        #pragma unroll
        for (int j = 0; j < 4; j++) {
            int k = 4 * t + j;
            hv[j] = (k < NBINS) ? *(volatile unsigned int*)&g_hist[k] : 0u;
            loc[j] = s;
            s += hv[j];
        }
        tsum[t] = s;
        __syncthreads();
        unsigned int v = tsum[t];
        unsigned int inc = v;
        #pragma unroll
        for (int o = 1; o < 32; o <<= 1) {
            unsigned int q = __shfl_up_sync(0xffffffffu, inc, o);
            if (lane >= o) inc += q;
        }
        if (lane == 31) wex[w + 1] = inc;
        __syncthreads();
        if (t == 0) {
            wex[0] = 0u;
            for (int j = 1; j < 8; j++) wex[j + 1] += wex[j];
        }
        __syncthreads();
        unsigned int base = wex[w] + inc - v;
        #pragma unroll
        for (int j = 0; j < 4; j++) {
            int k = 4 * t + j;
            if (k < NBINS) g_csum[k] = base + loc[j];
        }
        if (t == 255) {
            unsigned int tot = base + loc[3] + hv[3];
            g_csum[NBINS] = tot;
            g_total = tot;
        }
    }
}

// ---------------- reductions (16-warp blocks) ----------------
template <typename T>
__device__ __forceinline__ T warpSumT(T v) {
    #pragma unroll
    for (int o = 16; o; o >>= 1) v += __shfl_xor_sync(0xffffffffu, v, o);
    return v;
}
__device__ __forceinline__ unsigned int warpMaxU(unsigned int v) {
    #pragma unroll
    for (int o = 16; o; o >>= 1) v = max(v, __shfl_xor_sync(0xffffffffu, v, o));
    return v;
}
__device__ __forceinline__ double warpMaxD(double v) {
    #pragma unroll
    for (int o = 16; o; o >>= 1) v = fmax(v, __shfl_xor_sync(0xffffffffu, v, o));
    return v;
}

struct RedShared {
    double d[32];
    unsigned long long u[16];
};

__device__ __forceinline__ double blockSumD(double v, RedShared* sh) {
    int lane = threadIdx.x & 31, w = threadIdx.x >> 5;
    v = warpSumT(v);
    if (lane == 0) sh->d[w] = v;
    __syncthreads();
    if (w == 0) {
        double t = (lane < 16) ? sh->d[lane] : 0.0;
        t = warpSumT(t);
        if (lane == 0) sh->d[0] = t;
    }
    __syncthreads();
    double r = sh->d[0];
    __syncthreads();
    return r;
}
__device__ __forceinline__ void blockSum2(double& a, double& b, RedShared* sh) {
    int lane = threadIdx.x & 31, w = threadIdx.x >> 5;
    a = warpSumT(a); b = warpSumT(b);
    if (lane == 0) { sh->d[w] = a; sh->d[16 + w] = b; }
    __syncthreads();
    if (w == 0) {
        double ta = (lane < 16) ? sh->d[lane] : 0.0;
        double tb = (lane < 16) ? sh->d[16 + lane] : 0.0;
        ta = warpSumT(ta); tb = warpSumT(tb);
        if (lane == 0) { sh->d[0] = ta; sh->d[16] = tb; }
    }
    __syncthreads();
    a = sh->d[0]; b = sh->d[16];
    __syncthreads();
}
__device__ __forceinline__ void blockSumU_MaxD(unsigned int& s, double& mx, RedShared* sh) {
    int lane = threadIdx.x & 31, w = threadIdx.x >> 5;
    s = warpSumT(s); mx = warpMaxD(mx);
    if (lane == 0) { sh->u[w] = s; sh->d[w] = mx; }
    __syncthreads();
    if (w == 0) {
        unsigned int ts = (lane < 16) ? (unsigned int)sh->u[lane] : 0u;
        double tm = (lane < 16) ? sh->d[lane] : -1e300;
        ts = warpSumT(ts); tm = warpMaxD(tm);
        if (lane == 0) { sh->u[0] = ts; sh->d[0] = tm; }
    }
    __syncthreads();
    s = (unsigned int)sh->u[0]; mx = sh->d[0];
    __syncthreads();
}
__device__ __forceinline__ unsigned int blockMaxU(unsigned int v, RedShared* sh) {
    int lane = threadIdx.x & 31, w = threadIdx.x >> 5;
    v = warpMaxU(v);
    if (lane == 0) sh->u[w] = v;
    __syncthreads();
    if (w == 0) {
        unsigned int t = (lane < 16) ? (unsigned int)sh->u[lane] : 0u;
        t = warpMaxU(t);
        if (lane == 0) sh->u[0] = t;
    }
    __syncthreads();
    unsigned int r = (unsigned int)sh->u[0];
    __syncthreads();
    return r;
}

// ---------------- per-candidate KL (512 threads) + fused argmin/reset ----------------
__global__ void __launch_bounds__(KLT) kl_kernel(float* __restrict__ out) {
    const int i = IMIN + (int)blockIdx.x;
    const int L = 2 * i + 1;
    const int start = HALFB - i;
    const int stop = HALFB + i + 1;
    const int m = L / KQ;

    __shared__ unsigned int s_h[NBINS];
    __shared__ double s_q[KQ];
    __shared__ unsigned int s_nm[KQ];
    __shared__ RedShared s_red;

    for (int k = threadIdx.x; k < NBINS; k += KLT) s_h[k] = g_hist[k];
    __syncthreads();

    const unsigned int left = g_csum[start];
    const unsigned int right = g_total - g_csum[stop];

    unsigned int pv[2], vv[2];
    unsigned int mpi = 0u;
    #pragma unroll
    for (int t = 0; t < 2; t++) {
        int k = threadIdx.x + t * KLT;
        pv[t] = 0u; vv[t] = 0u;
        if (k < L) {
            unsigned int v = s_h[start + k];
            vv[t] = v;
            unsigned int p = v;
            if (k == 0) p += left;
            if (k == L - 1) p += right;
            pv[t] = p;
            mpi = max(mpi, p);
        }
    }
    mpi = blockMaxU(mpi, &s_red);
    const double mp = mpi ? (double)mpi : EPS_S;

    double qseg = 0.0;
    unsigned int nmj = 0u;
    if (threadIdx.x < KQ) {
        int j = threadIdx.x;
        int k0 = j * m;
        int k1 = (j == KQ - 1) ? L : (k0 + m);
        unsigned int sum = 0u, cnt = 0u;
        for (int k = k0; k < k1; k++) {
            unsigned int v = s_h[start + k];
            sum += v;
            cnt += (v != 0u && k != L - 1) ? 1u : 0u;
        }
        nmj = cnt;
        if (cnt > 0u) qseg = (double)sum / (double)cnt;
        s_q[j] = qseg;
        s_nm[j] = cnt;
    }
    unsigned int nnzq = nmj;
    double mq = (threadIdx.x < KQ && nmj > 0u) ? qseg : -1e300;
    blockSumU_MaxD(nnzq, mq, &s_red);
    mq = fmax(mq, EPS_S);

    double sq = 0.0;
    if (threadIdx.x < KQ && nmj > 0u) {
        double dq = qseg - mq;
        if (dq > EXP_CUT) sq = (double)nmj * exp(dq);
    }
    if (threadIdx.x == 0) {
        double dz = EPS_S - mq;
        if (dz > EXP_CUT) sq += (double)(L - (int)nnzq) * exp(dz);
    }
    double sp = 0.0;
    {
        double gate = mp + EXP_CUT;
        #pragma unroll
        for (int t = 0; t < 2; t++) {
            int k = threadIdx.x + t * KLT;
            if (k < L) {
                double pl = pv[t] ? (double)pv[t] : EPS_S;
                if (pl > gate) sp += exp(pl - mp);
            }
        }
    }
    blockSum2(sp, sq, &s_red);
    const double lZp = mp + log(sp);
    const double lZq = mq + log(sq);

    double kl = 0.0;
    {
        double gate = lZp + EXP_CUT;
        #pragma unroll
        for (int t = 0; t < 2; t++) {
            int k = threadIdx.x + t * KLT;
            if (k < L) {
                double pl = pv[t] ? (double)pv[t] : EPS_S;
                if (pl > gate) {
                    int seg = min(k / m, KQ - 1);
                    bool assigned = (vv[t] != 0u) && (k != L - 1) && (s_nm[seg] > 0u);
                    double ql = assigned ? s_q[seg] : EPS_S;
                    double lp = pl - lZp;
                    double lq = ql - lZq;
                    kl += exp(lp) * (lp - lq);
                }
            }
        }
    }
    kl = blockSumD(kl, &s_red);
    if (threadIdx.x == 0)
        g_kl[blockIdx.x] = (nnzq > 0u) ? kl : (double)INFINITY;

    // ---- fused argmin + output + global-state reset (last block) ----
    __shared__ unsigned int s_fin;
    __threadfence();
    if (threadIdx.x == 0)
        s_fin = (atomicAdd(&g_done2, 1u) == (unsigned int)(gridDim.x - 1)) ? 1u : 0u;
    __syncthreads();
    if (s_fin) {
        __threadfence();
        __shared__ double sv[KLT];
        __shared__ int si[KLT];
        double best = (double)INFINITY;
        int bi = 0x7fffffff;
        for (int k = threadIdx.x; k < NCAND; k += KLT) {
            double v = *(volatile double*)&g_kl[k];
            if (v < best || (v == best && k < bi)) { best = v; bi = k; }
        }
        sv[threadIdx.x] = best; si[threadIdx.x] = bi;
        __syncthreads();
        for (int s = KLT / 2; s > 0; s >>= 1) {
            if (threadIdx.x < s) {
                double vo = sv[threadIdx.x + s];
                int io = si[threadIdx.x + s];
                if (vo < sv[threadIdx.x] || (vo == sv[threadIdx.x] && io < si[threadIdx.x])) {
                    sv[threadIdx.x] = vo; si[threadIdx.x] = io;
                }
            }
            __syncthreads();
        }
        if (threadIdx.x == 0) {
            int ib = IMIN + si[0];
            float a = __uint_as_float(g_absmax_bits);
            double thr = -(double)a + 2.0 * (double)a * (double)(ib + HALFB + 1) / (double)NBINS;
            out[0] = (float)thr;
            g_absmax_bits = 0u;
            g_bar = 0u;
            g_done = 0u;
            g_done2 = 0u;
        }
        for (int k = threadIdx.x; k < NBINS; k += KLT) g_hist[k] = 0u;
    }
}

extern "C" void kernel_launch(void* const* d_in, const int* in_sizes, int n_in,
                              void* d_out, int out_size) {
    const float* x = (const float*)d_in[0];
    int n = in_sizes[0];
    main_kernel<<<MAIN_GRID, 256>>>(x, n);
    kl_kernel<<<NCAND, KLT>>>((float*)d_out);
}

// round 15
// speedup vs baseline: 1.3631x; 1.1420x over previous
#include <cuda_runtime.h>
#include <math.h>

#define NBINS 1001
#define KQ 127
#define HALFB 500
#define EPS_S 1e-4
#define IMIN 63
#define NCAND 438
#define HIST_SUB 4
#define EXP_CUT -700.0
#define BAND 2e-3f
#define MAIN_GRID 592   // 4 blocks/SM x 148 SMs; __launch_bounds__(256,4) guarantees residency
#define KL_WARPS 8
#define KL_BLOCKS ((NCAND + KL_WARPS - 1) / KL_WARPS)   // 55

__device__ unsigned int g_absmax_bits;   // zero at load; final kl block re-zeroes
__device__ unsigned int g_hist[NBINS];   // zero at load; final kl block re-zeroes
__device__ unsigned int g_csum[NBINS + 1];
__device__ unsigned int g_total;
__device__ unsigned int g_bar;           // grid barrier counter (reset by kl final block)
__device__ unsigned int g_done;          // hist scan ticket (reset by kl final block)
__device__ unsigned int g_done2;         // kl argmin ticket (reset by kl final block)
__device__ double g_kl[NCAND];

// ---------------- binning ----------------
__device__ __forceinline__ int bin_of(float c, float a, float inv, float step) {
    float y = __fmul_rn(__fadd_rn(c, a), inv);
    int b = (int)y;
    float fr = y - (float)b;
    if (fr < BAND || fr > 1.0f - BAND) {
        float e0 = __fadd_rn(__fmul_rn((float)b, step), -a);
        float e1 = __fadd_rn(__fmul_rn((float)(b + 1), step), -a);
        b += (c >= e1) ? 1 : 0;
        b -= (c < e0) ? 1 : 0;
    }
    return max(0, min(NBINS - 1, b));
}

// ---------------- fused absmax + grid barrier + histogram + scan (EXACT R10) ----------------
__global__ void __launch_bounds__(256, 4) main_kernel(const float* __restrict__ x, int n) {
    __shared__ unsigned int sh[HIST_SUB][NBINS];
    unsigned int* shf = &sh[0][0];
    for (int k = threadIdx.x; k < HIST_SUB * NBINS; k += 256) shf[k] = 0u;

    const int n4 = n >> 2;
    const float4* x4 = (const float4*)x;
    const int G = gridDim.x;
    const int b = blockIdx.x;
    const int lo = (int)((long long)b * n4 / G);
    const int hi = (int)((long long)(b + 1) * n4 / G);
    int lane = threadIdx.x & 31, w = threadIdx.x >> 5;

    // ---- phase 1: absmax over own chunk (forward sweep) ----
    float m = 0.f;
    for (int idx = lo + threadIdx.x; idx < hi; idx += 256) {
        float4 v = x4[idx];
        m = fmaxf(m, fmaxf(fmaxf(fabsf(v.x), fabsf(v.y)), fmaxf(fabsf(v.z), fabsf(v.w))));
    }
    if (b == 0 && threadIdx.x < (n & 3))
        m = fmaxf(m, fabsf(x[n4 * 4 + threadIdx.x]));
    #pragma unroll
    for (int o = 16; o; o >>= 1) m = fmaxf(m, __shfl_xor_sync(0xffffffffu, m, o));
    __shared__ float sm[8];
    if (lane == 0) sm[w] = m;
    __syncthreads();
    if (w == 0) {
        m = (lane < 8) ? sm[lane] : 0.f;
        #pragma unroll
        for (int o = 4; o; o >>= 1) m = fmaxf(m, __shfl_xor_sync(0xffffffffu, m, o));
        if (lane == 0) atomicMax(&g_absmax_bits, __float_as_uint(m));
    }

    // ---- grid barrier ----
    __threadfence();
    __syncthreads();
    if (threadIdx.x == 0) {
        atomicAdd(&g_bar, 1u);
        while (*(volatile unsigned int*)&g_bar < (unsigned int)G) { }
    }
    __syncthreads();

    const float a = __uint_as_float(*(volatile unsigned int*)&g_absmax_bits);
    const float step = __fdiv_rn(__fmul_rn(2.0f, a), (float)NBINS);
    const float inv = __fdiv_rn((float)NBINS, __fmul_rn(2.0f, a));
    unsigned int* hsub = sh[(threadIdx.x >> 5) & (HIST_SUB - 1)];

    // ---- phase 2: histogram over own chunk, REVERSE sweep (LIFO L2 reuse) ----
    for (int idx = hi - 1 - threadIdx.x; idx >= lo; idx -= 256) {
        float4 v = x4[idx];
        atomicAdd(&hsub[bin_of(v.x, a, inv, step)], 1u);
        atomicAdd(&hsub[bin_of(v.y, a, inv, step)], 1u);
        atomicAdd(&hsub[bin_of(v.z, a, inv, step)], 1u);
        atomicAdd(&hsub[bin_of(v.w, a, inv, step)], 1u);
    }
    if (b == 0 && threadIdx.x < (n & 3)) {
        float c = x[n4 * 4 + threadIdx.x];
        atomicAdd(&hsub[bin_of(c, a, inv, step)], 1u);
    }
    __syncthreads();
    for (int k = threadIdx.x; k < NBINS; k += 256) {
        unsigned int s = 0;
        #pragma unroll
        for (int j = 0; j < HIST_SUB; j++) s += sh[j][k];
        if (s) atomicAdd(&g_hist[k], s);
    }

    // ---- fused scan: last block builds exclusive prefix ----
    __shared__ unsigned int s_last;
    __threadfence();
    if (threadIdx.x == 0)
        s_last = (atomicAdd(&g_done, 1u) == (unsigned int)(G - 1)) ? 1u : 0u;
    __syncthreads();
    if (s_last) {
        __threadfence();
        __shared__ unsigned int tsum[256];
        __shared__ unsigned int wex[9];
        int t = threadIdx.x;
        unsigned int hv[4], loc[4];
        unsigned int s = 0;
        #pragma unroll
        for (int j = 0; j < 4; j++) {
            int k = 4 * t + j;
            hv[j] = (k < NBINS) ? *(volatile unsigned int*)&g_hist[k] : 0u;
            loc[j] = s;
            s += hv[j];
        }
        tsum[t] = s;
        __syncthreads();
        unsigned int v = tsum[t];
        unsigned int inc = v;
        #pragma unroll
        for (int o = 1; o < 32; o <<= 1) {
            unsigned int q = __shfl_up_sync(0xffffffffu, inc, o);
            if (lane >= o) inc += q;
        }
        if (lane == 31) wex[w + 1] = inc;
        __syncthreads();
        if (t == 0) {
            wex[0] = 0u;
            for (int j = 1; j < 8; j++) wex[j + 1] += wex[j];
        }
        __syncthreads();
        unsigned int base = wex[w] + inc - v;
        #pragma unroll
        for (int j = 0; j < 4; j++) {
            int k = 4 * t + j;
            if (k < NBINS) g_csum[k] = base + loc[j];
        }
        if (t == 255) {
            unsigned int tot = base + loc[3] + hv[3];
            g_csum[NBINS] = tot;
            g_total = tot;
        }
    }
}

// ---------------- warp reductions ----------------
template <typename T>
__device__ __forceinline__ T warpSumT(T v) {
    #pragma unroll
    for (int o = 16; o; o >>= 1) v += __shfl_xor_sync(0xffffffffu, v, o);
    return v;
}
__device__ __forceinline__ unsigned int warpMaxU(unsigned int v) {
    #pragma unroll
    for (int o = 16; o; o >>= 1) v = max(v, __shfl_xor_sync(0xffffffffu, v, o));
    return v;
}
__device__ __forceinline__ double warpMaxD(double v) {
    #pragma unroll
    for (int o = 16; o; o >>= 1) v = fmax(v, __shfl_xor_sync(0xffffffffu, v, o));
    return v;
}

// ---------------- per-candidate KL: ONE WARP PER CANDIDATE ----------------
// All reductions are warp shuffles; only one __syncthreads (hist smem load).
// assigned(v!=0 && k!=L-1) implies its segment count>0, so s_nm is unnecessary.
__global__ void __launch_bounds__(KL_WARPS * 32) kl_kernel(float* __restrict__ out) {
    __shared__ unsigned int s_h[NBINS];
    __shared__ double s_q[KL_WARPS][KQ + 1];   // +1 pad
    const int lane = threadIdx.x & 31;
    const int wid = threadIdx.x >> 5;

    for (int k = threadIdx.x; k < NBINS; k += KL_WARPS * 32) s_h[k] = g_hist[k];
    __syncthreads();

    const int cand = (int)blockIdx.x * KL_WARPS + wid;
    if (cand < NCAND) {
        const int i = IMIN + cand;
        const int L = 2 * i + 1;
        const int start = HALFB - i;
        const int stop = HALFB + i + 1;
        const int m = L / KQ;
        const unsigned int left = g_csum[start];
        const unsigned int right = g_total - g_csum[stop];
        const int jmax = (L + 31) >> 5;
        double* q_w = s_q[wid];

        // pass 1: max p (strided bins: conflict-free)
        unsigned int mpi = 0u;
        for (int j = 0; j < jmax; j++) {
            int k = lane + (j << 5);
            if (k < L) {
                unsigned int p = s_h[start + k];
                if (k == 0) p += left;
                if (k == L - 1) p += right;
                mpi = max(mpi, p);
            }
        }
        mpi = warpMaxU(mpi);
        const double mp = mpi ? (double)mpi : EPS_S;

        // segment pass: lane owns segments lane, lane+32, ... (<=4)
        double qs[4];
        unsigned int nms[4];
        unsigned int nnz = 0u;
        double mq = -1e300;
        int si = 0;
        for (int s = lane; s < KQ; s += 32, si++) {
            int k0 = s * m;
            int k1 = (s == KQ - 1) ? L : (k0 + m);
            unsigned int sum = 0u, cnt = 0u;
            for (int k = k0; k < k1; k++) {
                unsigned int v = s_h[start + k];
                sum += v;
                cnt += (v != 0u && k != L - 1) ? 1u : 0u;
            }
            double q = cnt ? (double)sum / (double)cnt : 0.0;
            q_w[s] = q;
            qs[si] = q; nms[si] = cnt;
            nnz += cnt;
            if (cnt) mq = fmax(mq, q);
        }
        for (; si < 4; si++) { qs[si] = 0.0; nms[si] = 0u; }
        nnz = warpSumT(nnz);
        mq = warpMaxD(mq);
        mq = fmax(mq, EPS_S);   // zero-q bins always exist (k=L-1)

        // sq: grouped per-segment + zero-q bins
        double sq = 0.0;
        #pragma unroll
        for (int t = 0; t < 4; t++) {
            if (nms[t]) {
                double dq = qs[t] - mq;
                if (dq > EXP_CUT) sq += (double)nms[t] * exp(dq);
            }
        }
        if (lane == 0) {
            double dz = EPS_S - mq;
            if (dz > EXP_CUT) sq += (double)(L - (int)nnz) * exp(dz);
        }
        // sp pass
        double sp = 0.0;
        {
            double gate = mp + EXP_CUT;
            for (int j = 0; j < jmax; j++) {
                int k = lane + (j << 5);
                if (k < L) {
                    unsigned int p = s_h[start + k];
                    if (k == 0) p += left;
                    if (k == L - 1) p += right;
                    double pl = p ? (double)p : EPS_S;
                    if (pl > gate) sp += exp(pl - mp);
                }
            }
        }
        sp = warpSumT(sp);
        sq = warpSumT(sq);
        const double lZp = mp + log(sp);
        const double lZq = mq + log(sq);

        // kl pass
        double kl = 0.0;
        {
            double gate = lZp + EXP_CUT;
            for (int j = 0; j < jmax; j++) {
                int k = lane + (j << 5);
                if (k < L) {
                    unsigned int v = s_h[start + k];
                    unsigned int p = v;
                    if (k == 0) p += left;
                    if (k == L - 1) p += right;
                    double pl = p ? (double)p : EPS_S;
                    if (pl > gate) {
                        int seg = min(k / m, KQ - 1);
                        bool assigned = (v != 0u) && (k != L - 1);
                        double ql = assigned ? q_w[seg] : EPS_S;
                        double lp = pl - lZp;
                        double lq = ql - lZq;
                        kl += exp(lp) * (lp - lq);
                    }
                }
            }
        }
        kl = warpSumT(kl);
        if (lane == 0)
            g_kl[cand] = (nnz > 0u) ? kl : (double)INFINITY;
    }

    // ---- fused argmin + output + global-state reset (last block) ----
    __shared__ unsigned int s_fin;
    __syncthreads();           // all warps' g_kl writes issued
    __threadfence();
    if (threadIdx.x == 0)
        s_fin = (atomicAdd(&g_done2, 1u) == (unsigned int)(gridDim.x - 1)) ? 1u : 0u;
    __syncthreads();
    if (s_fin) {
        __threadfence();
        __shared__ double sv[KL_WARPS * 32];
        __shared__ int si2[KL_WARPS * 32];
        double best = (double)INFINITY;
        int bi = 0x7fffffff;
        for (int k = threadIdx.x; k < NCAND; k += KL_WARPS * 32) {
            double v = *(volatile double*)&g_kl[k];
            if (v < best || (v == best && k < bi)) { best = v; bi = k; }
        }
        sv[threadIdx.x] = best; si2[threadIdx.x] = bi;
        __syncthreads();
        for (int s = KL_WARPS * 16; s > 0; s >>= 1) {
            if (threadIdx.x < s) {
                double vo = sv[threadIdx.x + s];
                int io = si2[threadIdx.x + s];
                if (vo < sv[threadIdx.x] || (vo == sv[threadIdx.x] && io < si2[threadIdx.x])) {
                    sv[threadIdx.x] = vo; si2[threadIdx.x] = io;
                }
            }
            __syncthreads();
        }
        if (threadIdx.x == 0) {
            int ib = IMIN + si2[0];
            float a = __uint_as_float(g_absmax_bits);
            double thr = -(double)a + 2.0 * (double)a * (double)(ib + HALFB + 1) / (double)NBINS;
            out[0] = (float)thr;
            g_absmax_bits = 0u;
            g_bar = 0u;
            g_done = 0u;
            g_done2 = 0u;
        }
        for (int k = threadIdx.x; k < NBINS; k += KL_WARPS * 32) g_hist[k] = 0u;
    }
}

extern "C" void kernel_launch(void* const* d_in, const int* in_sizes, int n_in,
                              void* d_out, int out_size) {
    const float* x = (const float*)d_in[0];
    int n = in_sizes[0];
    main_kernel<<<MAIN_GRID, 256>>>(x, n);
    kl_kernel<<<KL_BLOCKS, KL_WARPS * 32>>>((float*)d_out);
}

// round 16
// speedup vs baseline: 1.6028x; 1.1759x over previous
#include <cuda_runtime.h>
#include <math.h>

#define NBINS 1001
#define KQ 127
#define HALFB 500
#define EPS_S 1e-4
#define IMIN 63
#define NCAND 438
#define HIST_SUB 4
#define EXP_CUT -80.0
#define BAND 2e-3f
#define MAIN_GRID 592   // 4 blocks/SM x 148 SMs; __launch_bounds__(256,4) guarantees residency
#define KL_WARPS 2
#define KL_BLOCKS ((NCAND + KL_WARPS - 1) / KL_WARPS)   // 219

__device__ unsigned int g_absmax_bits;   // zero at load; final kl block re-zeroes
__device__ unsigned int g_hist[NBINS];   // zero at load; final kl block re-zeroes
__device__ unsigned int g_csum[NBINS + 1];
__device__ unsigned int g_total;
__device__ unsigned int g_bar;           // grid barrier counter (reset by kl final block)
__device__ unsigned int g_done;          // hist scan ticket (reset by kl final block)
__device__ unsigned int g_done2;         // kl argmin ticket (reset by kl final block)
__device__ double g_kl[NCAND];

// ---------------- binning ----------------
__device__ __forceinline__ int bin_of(float c, float a, float inv, float step) {
    float y = __fmul_rn(__fadd_rn(c, a), inv);
    int b = (int)y;
    float fr = y - (float)b;
    if (fr < BAND || fr > 1.0f - BAND) {
        float e0 = __fadd_rn(__fmul_rn((float)b, step), -a);
        float e1 = __fadd_rn(__fmul_rn((float)(b + 1), step), -a);
        b += (c >= e1) ? 1 : 0;
        b -= (c < e0) ? 1 : 0;
    }
    return max(0, min(NBINS - 1, b));
}

// ---------------- fused absmax + grid barrier + histogram + scan (EXACT R10) ----------------
__global__ void __launch_bounds__(256, 4) main_kernel(const float* __restrict__ x, int n) {
    __shared__ unsigned int sh[HIST_SUB][NBINS];
    unsigned int* shf = &sh[0][0];
    for (int k = threadIdx.x; k < HIST_SUB * NBINS; k += 256) shf[k] = 0u;

    const int n4 = n >> 2;
    const float4* x4 = (const float4*)x;
    const int G = gridDim.x;
    const int b = blockIdx.x;
    const int lo = (int)((long long)b * n4 / G);
    const int hi = (int)((long long)(b + 1) * n4 / G);
    int lane = threadIdx.x & 31, w = threadIdx.x >> 5;

    // ---- phase 1: absmax over own chunk ----
    float m = 0.f;
    for (int idx = lo + threadIdx.x; idx < hi; idx += 256) {
        float4 v = x4[idx];
        m = fmaxf(m, fmaxf(fmaxf(fabsf(v.x), fabsf(v.y)), fmaxf(fabsf(v.z), fabsf(v.w))));
    }
    if (b == 0 && threadIdx.x < (n & 3))
        m = fmaxf(m, fabsf(x[n4 * 4 + threadIdx.x]));
    #pragma unroll
    for (int o = 16; o; o >>= 1) m = fmaxf(m, __shfl_xor_sync(0xffffffffu, m, o));
    __shared__ float sm[8];
    if (lane == 0) sm[w] = m;
    __syncthreads();
    if (w == 0) {
        m = (lane < 8) ? sm[lane] : 0.f;
        #pragma unroll
        for (int o = 4; o; o >>= 1) m = fmaxf(m, __shfl_xor_sync(0xffffffffu, m, o));
        if (lane == 0) atomicMax(&g_absmax_bits, __float_as_uint(m));
    }

    // ---- grid barrier ----
    __threadfence();
    __syncthreads();
    if (threadIdx.x == 0) {
        atomicAdd(&g_bar, 1u);
        while (*(volatile unsigned int*)&g_bar < (unsigned int)G) { }
    }
    __syncthreads();

    const float a = __uint_as_float(*(volatile unsigned int*)&g_absmax_bits);
    const float step = __fdiv_rn(__fmul_rn(2.0f, a), (float)NBINS);
    const float inv = __fdiv_rn((float)NBINS, __fmul_rn(2.0f, a));
    unsigned int* hsub = sh[(threadIdx.x >> 5) & (HIST_SUB - 1)];

    // ---- phase 2: histogram, REVERSE sweep (LIFO L2 reuse) ----
    for (int idx = hi - 1 - threadIdx.x; idx >= lo; idx -= 256) {
        float4 v = x4[idx];
        atomicAdd(&hsub[bin_of(v.x, a, inv, step)], 1u);
        atomicAdd(&hsub[bin_of(v.y, a, inv, step)], 1u);
        atomicAdd(&hsub[bin_of(v.z, a, inv, step)], 1u);
        atomicAdd(&hsub[bin_of(v.w, a, inv, step)], 1u);
    }
    if (b == 0 && threadIdx.x < (n & 3)) {
        float c = x[n4 * 4 + threadIdx.x];
        atomicAdd(&hsub[bin_of(c, a, inv, step)], 1u);
    }
    __syncthreads();
    for (int k = threadIdx.x; k < NBINS; k += 256) {
        unsigned int s = 0;
        #pragma unroll
        for (int j = 0; j < HIST_SUB; j++) s += sh[j][k];
        if (s) atomicAdd(&g_hist[k], s);
    }

    // ---- fused scan: last block builds exclusive prefix ----
    __shared__ unsigned int s_last;
    __threadfence();
    if (threadIdx.x == 0)
        s_last = (atomicAdd(&g_done, 1u) == (unsigned int)(G - 1)) ? 1u : 0u;
    __syncthreads();
    if (s_last) {
        __threadfence();
        __shared__ unsigned int tsum[256];
        __shared__ unsigned int wex[9];
        int t = threadIdx.x;
        unsigned int hv[4], loc[4];
        unsigned int s = 0;
        #pragma unroll
        for (int j = 0; j < 4; j++) {
            int k = 4 * t + j;
            hv[j] = (k < NBINS) ? *(volatile unsigned int*)&g_hist[k] : 0u;
            loc[j] = s;
            s += hv[j];
        }
        tsum[t] = s;
        __syncthreads();
        unsigned int v = tsum[t];
        unsigned int inc = v;
        #pragma unroll
        for (int o = 1; o < 32; o <<= 1) {
            unsigned int q = __shfl_up_sync(0xffffffffu, inc, o);
            if (lane >= o) inc += q;
        }
        if (lane == 31) wex[w + 1] = inc;
        __syncthreads();
        if (t == 0) {
            wex[0] = 0u;
            for (int j = 1; j < 8; j++) wex[j + 1] += wex[j];
        }
        __syncthreads();
        unsigned int base = wex[w] + inc - v;
        #pragma unroll
        for (int j = 0; j < 4; j++) {
            int k = 4 * t + j;
            if (k < NBINS) g_csum[k] = base + loc[j];
        }
        if (t == 255) {
            unsigned int tot = base + loc[3] + hv[3];
            g_csum[NBINS] = tot;
            g_total = tot;
        }
    }
}

// ---------------- warp reductions ----------------
template <typename T>
__device__ __forceinline__ T warpSumT(T v) {
    #pragma unroll
    for (int o = 16; o; o >>= 1) v += __shfl_xor_sync(0xffffffffu, v, o);
    return v;
}
__device__ __forceinline__ unsigned int warpMaxU(unsigned int v) {
    #pragma unroll
    for (int o = 16; o; o >>= 1) v = max(v, __shfl_xor_sync(0xffffffffu, v, o));
    return v;
}
__device__ __forceinline__ double warpMaxD(double v) {
    #pragma unroll
    for (int o = 16; o; o >>= 1) v = fmax(v, __shfl_xor_sync(0xffffffffu, v, o));
    return v;
}

// fast exp: fp32 expf on a double arg known to be in [-80, 0].
// rel err ~2 ulp fp32 (2e-7); skipped terms (< e^-80) contribute < 2e-32.
__device__ __forceinline__ double exp_fast(double x) {
    return (double)expf((float)x);
}

// ---------------- per-candidate KL: ONE WARP PER CANDIDATE, fp32 transcendentals ----------------
__global__ void __launch_bounds__(KL_WARPS * 32) kl_kernel(float* __restrict__ out) {
    __shared__ unsigned int s_h[NBINS];
    __shared__ double s_q[KL_WARPS][KQ + 1];
    const int lane = threadIdx.x & 31;
    const int wid = threadIdx.x >> 5;

    for (int k = threadIdx.x; k < NBINS; k += KL_WARPS * 32) s_h[k] = g_hist[k];
    __syncthreads();

    const int cand = (int)blockIdx.x * KL_WARPS + wid;
    if (cand < NCAND) {
        const int i = IMIN + cand;
        const int L = 2 * i + 1;
        const int start = HALFB - i;
        const int stop = HALFB + i + 1;
        const int m = L / KQ;
        const unsigned int left = g_csum[start];
        const unsigned int right = g_total - g_csum[stop];
        const int jmax = (L + 31) >> 5;
        double* q_w = s_q[wid];

        // pass 1: max p
        unsigned int mpi = 0u;
        for (int j = 0; j < jmax; j++) {
            int k = lane + (j << 5);
            if (k < L) {
                unsigned int p = s_h[start + k];
                if (k == 0) p += left;
                if (k == L - 1) p += right;
                mpi = max(mpi, p);
            }
        }
        mpi = warpMaxU(mpi);
        const double mp = mpi ? (double)mpi : EPS_S;

        // segment pass: lane owns segments lane, lane+32, ... (<=4)
        double qs[4];
        unsigned int nms[4];
        unsigned int nnz = 0u;
        double mq = -1e300;
        int si = 0;
        for (int s = lane; s < KQ; s += 32, si++) {
            int k0 = s * m;
            int k1 = (s == KQ - 1) ? L : (k0 + m);
            unsigned int sum = 0u, cnt = 0u;
            for (int k = k0; k < k1; k++) {
                unsigned int v = s_h[start + k];
                sum += v;
                cnt += (v != 0u && k != L - 1) ? 1u : 0u;
            }
            double q = cnt ? (double)sum / (double)cnt : 0.0;
            q_w[s] = q;
            qs[si] = q; nms[si] = cnt;
            nnz += cnt;
            if (cnt) mq = fmax(mq, q);
        }
        for (; si < 4; si++) { qs[si] = 0.0; nms[si] = 0u; }
        nnz = warpSumT(nnz);
        mq = warpMaxD(mq);
        mq = fmax(mq, EPS_S);

        // sq: grouped per-segment + zero-q bins
        double sq = 0.0;
        #pragma unroll
        for (int t = 0; t < 4; t++) {
            if (nms[t]) {
                double dq = qs[t] - mq;
                if (dq > EXP_CUT) sq += (double)nms[t] * exp_fast(dq);
            }
        }
        if (lane == 0) {
            double dz = EPS_S - mq;
            if (dz > EXP_CUT) sq += (double)(L - (int)nnz) * exp_fast(dz);
        }
        // sp pass
        double sp = 0.0;
        {
            double gate = mp + EXP_CUT;
            for (int j = 0; j < jmax; j++) {
                int k = lane + (j << 5);
                if (k < L) {
                    unsigned int p = s_h[start + k];
                    if (k == 0) p += left;
                    if (k == L - 1) p += right;
                    double pl = p ? (double)p : EPS_S;
                    if (pl > gate) sp += exp_fast(pl - mp);
                }
            }
        }
        sp = warpSumT(sp);
        sq = warpSumT(sq);
        const double lZp = mp + (double)logf((float)sp);
        const double lZq = mq + (double)logf((float)sq);

        // kl pass
        double kl = 0.0;
        {
            double gate = lZp + EXP_CUT;
            for (int j = 0; j < jmax; j++) {
                int k = lane + (j << 5);
                if (k < L) {
                    unsigned int v = s_h[start + k];
                    unsigned int p = v;
                    if (k == 0) p += left;
                    if (k == L - 1) p += right;
                    double pl = p ? (double)p : EPS_S;
                    if (pl > gate) {
                        int seg = min(k / m, KQ - 1);
                        bool assigned = (v != 0u) && (k != L - 1);
                        double ql = assigned ? q_w[seg] : EPS_S;
                        double lp = pl - lZp;
                        double lq = ql - lZq;
                        kl += exp_fast(lp) * (lp - lq);
                    }
                }
            }
        }
        kl = warpSumT(kl);
        if (lane == 0)
            g_kl[cand] = (nnz > 0u) ? kl : (double)INFINITY;
    }

    // ---- fused argmin + output + global-state reset (last block) ----
    __shared__ unsigned int s_fin;
    __syncthreads();
    __threadfence();
    if (threadIdx.x == 0)
        s_fin = (atomicAdd(&g_done2, 1u) == (unsigned int)(gridDim.x - 1)) ? 1u : 0u;
    __syncthreads();
    if (s_fin) {
        __threadfence();
        __shared__ double sv[KL_WARPS * 32];
        __shared__ int si2[KL_WARPS * 32];
        double best = (double)INFINITY;
        int bi = 0x7fffffff;
        for (int k = threadIdx.x; k < NCAND; k += KL_WARPS * 32) {
            double v = *(volatile double*)&g_kl[k];
            if (v < best || (v == best && k < bi)) { best = v; bi = k; }
        }
        sv[threadIdx.x] = best; si2[threadIdx.x] = bi;
        __syncthreads();
        for (int s = KL_WARPS * 16; s > 0; s >>= 1) {
            if (threadIdx.x < s) {
                double vo = sv[threadIdx.x + s];
                int io = si2[threadIdx.x + s];
                if (vo < sv[threadIdx.x] || (vo == sv[threadIdx.x] && io < si2[threadIdx.x])) {
                    sv[threadIdx.x] = vo; si2[threadIdx.x] = io;
                }
            }
            __syncthreads();
        }
        if (threadIdx.x == 0) {
            int ib = IMIN + si2[0];
            float a = __uint_as_float(g_absmax_bits);
            double thr = -(double)a + 2.0 * (double)a * (double)(ib + HALFB + 1) / (double)NBINS;
            out[0] = (float)thr;
            g_absmax_bits = 0u;
            g_bar = 0u;
            g_done = 0u;
            g_done2 = 0u;
        }
        for (int k = threadIdx.x; k < NBINS; k += KL_WARPS * 32) g_hist[k] = 0u;
    }
}

extern "C" void kernel_launch(void* const* d_in, const int* in_sizes, int n_in,
                              void* d_out, int out_size) {
    const float* x = (const float*)d_in[0];
    int n = in_sizes[0];
    main_kernel<<<MAIN_GRID, 256>>>(x, n);
    kl_kernel<<<KL_BLOCKS, KL_WARPS * 32>>>((float*)d_out);
}